// round 10
// baseline (speedup 1.0000x reference)
#include <cuda_runtime.h>
#include <cstdint>

#define Bn 1024
#define Cn 1024
#define NP 64    // H*W
#define NH 16
#define HD 64
#define CP (Cn * NP)   // 65536 elements per batch image

// ---------------- scratch (device globals; no allocation allowed) ----------------
__device__ __align__(16) float g_qkv[(size_t)3 * Bn * CP];   // [b][w][c][p]
__device__ __align__(16) float g_attn[(size_t)Bn * CP];      // attention output, pre-proj
__device__ __align__(16) float g_res[(size_t)Bn * CP];       // residual output, pre-LN
__device__ float g_psum[Bn * 8];
__device__ float g_psumsq[Bn * 8];
__device__ float g_mean[Bn];
__device__ float g_rinv[Bn];

// ---------------- core SGEMM: (128 x 1024) @ (1024 x 64) -------------------------
// A: 128 rows, ld=1024 (row-major). X: 1024x64 row-major. 256 threads.
// Thread (ty=tid>>4, tx=tid&15) owns rows {ty*4..+3, 64+ty*4..+3}, cols tx*4..+3.
__device__ __forceinline__ void gemm_1024(
    const float* __restrict__ A,
    const float* __restrict__ X,
    float acc[2][4][4],
    float* As, float* Bs, int tid)
{
    const int tx = tid & 15;
    const int ty = tid >> 4;
    float4 pa[4], pb[2];
#pragma unroll
    for (int i = 0; i < 4; ++i) {
        int f = tid + i * 256;
        pa[i] = *reinterpret_cast<const float4*>(A + (size_t)(f >> 3) * 1024 + (f & 7) * 4);
    }
#pragma unroll
    for (int i = 0; i < 2; ++i) {
        int f = tid + i * 256;
        pb[i] = *reinterpret_cast<const float4*>(X + (f >> 4) * 64 + (f & 15) * 4);
    }
    for (int kc = 0; kc < 1024; kc += 32) {
#pragma unroll
        for (int i = 0; i < 4; ++i) {
            int f = tid + i * 256;
            int ar = f >> 3, ac = (f & 7) * 4;
            As[(ac + 0) * 128 + ar] = pa[i].x;
            As[(ac + 1) * 128 + ar] = pa[i].y;
            As[(ac + 2) * 128 + ar] = pa[i].z;
            As[(ac + 3) * 128 + ar] = pa[i].w;
        }
#pragma unroll
        for (int i = 0; i < 2; ++i) {
            int f = tid + i * 256;
            *reinterpret_cast<float4*>(Bs + (f >> 4) * 64 + (f & 15) * 4) = pb[i];
        }
        __syncthreads();
        if (kc + 32 < 1024) {
#pragma unroll
            for (int i = 0; i < 4; ++i) {
                int f = tid + i * 256;
                pa[i] = *reinterpret_cast<const float4*>(
                    A + (size_t)(f >> 3) * 1024 + (kc + 32) + (f & 7) * 4);
            }
#pragma unroll
            for (int i = 0; i < 2; ++i) {
                int f = tid + i * 256;
                pb[i] = *reinterpret_cast<const float4*>(
                    X + (kc + 32 + (f >> 4)) * 64 + (f & 15) * 4);
            }
        }
#pragma unroll 16
        for (int kk = 0; kk < 32; ++kk) {
            float4 a0 = *reinterpret_cast<const float4*>(As + kk * 128 + ty * 4);
            float4 a1 = *reinterpret_cast<const float4*>(As + kk * 128 + 64 + ty * 4);
            float4 b0 = *reinterpret_cast<const float4*>(Bs + kk * 64 + tx * 4);
            float av0[4] = {a0.x, a0.y, a0.z, a0.w};
            float av1[4] = {a1.x, a1.y, a1.z, a1.w};
            float bv[4]  = {b0.x, b0.y, b0.z, b0.w};
#pragma unroll
            for (int i = 0; i < 4; ++i)
#pragma unroll
                for (int j = 0; j < 4; ++j) {
                    acc[0][i][j] = fmaf(av0[i], bv[j], acc[0][i][j]);
                    acc[1][i][j] = fmaf(av1[i], bv[j], acc[1][i][j]);
                }
        }
        __syncthreads();
    }
}

// ---------------- K1: fused QKV projection ---------------------------------------
__global__ __launch_bounds__(256) void k_qkv(
    const float* __restrict__ x,
    const float* __restrict__ Wq, const float* __restrict__ bq,
    const float* __restrict__ Wk, const float* __restrict__ bk,
    const float* __restrict__ Wv, const float* __restrict__ bv)
{
    __shared__ __align__(16) float As[32 * 128];
    __shared__ __align__(16) float Bs[32 * 64];
    const int tid = threadIdx.x;
    const int b = blockIdx.x;
    const int tile = blockIdx.y;          // 0..23
    const int w = tile >> 3;              // 0:q 1:k 2:v
    const int row0 = (tile & 7) * 128;
    const float* W    = (w == 0) ? Wq : (w == 1) ? Wk : Wv;
    const float* bias = (w == 0) ? bq : (w == 1) ? bk : bv;
    const float* X = x + (size_t)b * CP;

    float acc[2][4][4] = {};
    gemm_1024(W + (size_t)row0 * 1024, X, acc, As, Bs, tid);

    const int tx = tid & 15, ty = tid >> 4;
    float* out = g_qkv + ((size_t)b * 3 + w) * CP;
#pragma unroll
    for (int h2 = 0; h2 < 2; ++h2)
#pragma unroll
        for (int i = 0; i < 4; ++i) {
            int r = row0 + h2 * 64 + ty * 4 + i;
            float bb = bias[r];
            float4 o = make_float4(acc[h2][i][0] + bb, acc[h2][i][1] + bb,
                                   acc[h2][i][2] + bb, acc[h2][i][3] + bb);
            *reinterpret_cast<float4*>(out + (size_t)r * 64 + tx * 4) = o;
        }
}

// ---------------- K2: per-(batch, head) attention --------------------------------
__global__ __launch_bounds__(256) void k_attn(const float* __restrict__ temperature)
{
    __shared__ __align__(16) float S0[4096];   // q -> (reduction scratch) -> v (swizzled transpose)
    __shared__ __align__(16) float S1[4096];   // k
    __shared__ __align__(16) float S2[4096];   // attn^T [m][n]
    const int tid = threadIdx.x;
    const int bh = blockIdx.x;
    const int b = bh >> 4, h = bh & 15;
    const float* qg = g_qkv + ((size_t)b * 3 + 0) * CP + h * 4096;
    const float* kg = g_qkv + ((size_t)b * 3 + 1) * CP + h * 4096;
    const float* vg = g_qkv + ((size_t)b * 3 + 2) * CP + h * 4096;

    // load q, k (64x64 each)
#pragma unroll
    for (int i = 0; i < 4; ++i) {
        int f = tid + i * 256;
        reinterpret_cast<float4*>(S0)[f] = reinterpret_cast<const float4*>(qg)[f];
        reinterpret_cast<float4*>(S1)[f] = reinterpret_cast<const float4*>(kg)[f];
    }
    __syncthreads();

    // L2-normalize each row (over the 64 spatial positions), q and k
    if (tid < 128) {
        float* mat = (tid < 64) ? S0 : S1;
        int r = tid & 63;
        float s = 0.f;
        for (int i = 0; i < 64; ++i) { int p = (i + r) & 63; float v = mat[r * 64 + p]; s = fmaf(v, v, s); }
        float inv = 1.0f / fmaxf(sqrtf(s), 1e-12f);
        for (int i = 0; i < 64; ++i) { int p = (i + r) & 63; mat[r * 64 + p] *= inv; }
    }
    __syncthreads();

    const float invT = 1.0f / (temperature[0] + 1e-6f);
    const int tx = tid & 15, ty = tid >> 4;

    // attn^T[m][n] = invT * sum_d k[d][m] q[d][n]   -> S2
    {
        float a[4][4] = {};
        const int n0 = tx * 4, m0 = ty * 4;
#pragma unroll 8
        for (int d = 0; d < 64; ++d) {
            float4 kf = *reinterpret_cast<const float4*>(S1 + d * 64 + m0);
            float4 qf = *reinterpret_cast<const float4*>(S0 + d * 64 + n0);
            float kv[4] = {kf.x, kf.y, kf.z, kf.w};
            float qv[4] = {qf.x, qf.y, qf.z, qf.w};
#pragma unroll
            for (int i = 0; i < 4; ++i)
#pragma unroll
                for (int j = 0; j < 4; ++j)
                    a[i][j] = fmaf(kv[i], qv[j], a[i][j]);
        }
#pragma unroll
        for (int i = 0; i < 4; ++i)
            *reinterpret_cast<float4*>(S2 + (m0 + i) * 64 + n0) =
                make_float4(a[i][0] * invT, a[i][1] * invT, a[i][2] * invT, a[i][3] * invT);
    }
    __syncthreads();

    // softmax over m (first index of S2), per column n; S0 reused as reduction scratch
    {
        const int n = tid & 63, sub = tid >> 6;   // 4 sub-threads per column
        float mx = -1e30f;
#pragma unroll
        for (int i = 0; i < 16; ++i) mx = fmaxf(mx, S2[(sub * 16 + i) * 64 + n]);
        S0[sub * 64 + n] = mx;
        __syncthreads();
        float gmx = fmaxf(fmaxf(S0[n], S0[64 + n]), fmaxf(S0[128 + n], S0[192 + n]));
        __syncthreads();
        float s = 0.f;
#pragma unroll
        for (int i = 0; i < 16; ++i) {
            float e = __expf(S2[(sub * 16 + i) * 64 + n] - gmx);
            S2[(sub * 16 + i) * 64 + n] = e;
            s += e;
        }
        S0[sub * 64 + n] = s;
        __syncthreads();
        float inv = 1.0f / (S0[n] + S0[64 + n] + S0[128 + n] + S0[192 + n]);
#pragma unroll
        for (int i = 0; i < 16; ++i) S2[(sub * 16 + i) * 64 + n] *= inv;
    }
    __syncthreads();

    // load V transposed + XOR-swizzled into S0: S0[p][d ^ 4*(p&7)] = v[d][p]
#pragma unroll
    for (int i = 0; i < 4; ++i) {
        int f = tid + i * 256;
        int d = f >> 4, p4 = (f & 15) * 4;
        float4 vv = reinterpret_cast<const float4*>(vg)[f];
        S0[(p4 + 0) * 64 + (d ^ (((p4 + 0) & 7) * 4))] = vv.x;
        S0[(p4 + 1) * 64 + (d ^ (((p4 + 1) & 7) * 4))] = vv.y;
        S0[(p4 + 2) * 64 + (d ^ (((p4 + 2) & 7) * 4))] = vv.z;
        S0[(p4 + 3) * 64 + (d ^ (((p4 + 3) & 7) * 4))] = vv.w;
    }
    __syncthreads();

    // out[d][n] = sum_m v[d][m] * attn^T[m][n]
    {
        const int n0 = tx * 4, d0 = ty * 4;
        float o[4][4] = {};
#pragma unroll 8
        for (int m = 0; m < 64; ++m) {
            float4 vf = *reinterpret_cast<const float4*>(S0 + m * 64 + (d0 ^ ((m & 7) * 4)));
            float4 af = *reinterpret_cast<const float4*>(S2 + m * 64 + n0);
            float vv[4] = {vf.x, vf.y, vf.z, vf.w};
            float aa[4] = {af.x, af.y, af.z, af.w};
#pragma unroll
            for (int i = 0; i < 4; ++i)
#pragma unroll
                for (int j = 0; j < 4; ++j)
                    o[i][j] = fmaf(vv[i], aa[j], o[i][j]);
        }
        float* og = g_attn + (size_t)b * CP + h * 4096;
#pragma unroll
        for (int i = 0; i < 4; ++i)
            *reinterpret_cast<float4*>(og + (d0 + i) * 64 + n0) =
                make_float4(o[i][0], o[i][1], o[i][2], o[i][3]);
    }
}

// ---------------- K3: output projection + residual + LN partials ------------------
__global__ __launch_bounds__(256) void k_proj(
    const float* __restrict__ x,
    const float* __restrict__ Wp, const float* __restrict__ bp,
    const float* __restrict__ gamma)
{
    __shared__ __align__(16) float As[32 * 128];
    __shared__ __align__(16) float Bs[32 * 64];
    __shared__ float red[16];
    const int tid = threadIdx.x;
    const int b = blockIdx.x;
    const int tile = blockIdx.y;   // 0..7
    const int row0 = tile * 128;
    const float* X = g_attn + (size_t)b * CP;

    float acc[2][4][4] = {};
    gemm_1024(Wp + (size_t)row0 * 1024, X, acc, As, Bs, tid);

    const int tx = tid & 15, ty = tid >> 4;
    const float g = gamma[0];
    const float g1 = 1.0f - g;
    float ls = 0.f, lq = 0.f;
    float* out = g_res + (size_t)b * CP;
    const float* xb = x + (size_t)b * CP;
#pragma unroll
    for (int h2 = 0; h2 < 2; ++h2)
#pragma unroll
        for (int i = 0; i < 4; ++i) {
            int r = row0 + h2 * 64 + ty * 4 + i;
            float bb = bp[r];
            float4 xr = *reinterpret_cast<const float4*>(xb + (size_t)r * 64 + tx * 4);
            float4 o;
            o.x = g * (acc[h2][i][0] + bb) + g1 * xr.x;
            o.y = g * (acc[h2][i][1] + bb) + g1 * xr.y;
            o.z = g * (acc[h2][i][2] + bb) + g1 * xr.z;
            o.w = g * (acc[h2][i][3] + bb) + g1 * xr.w;
            *reinterpret_cast<float4*>(out + (size_t)r * 64 + tx * 4) = o;
            ls += o.x + o.y + o.z + o.w;
            lq += o.x * o.x + o.y * o.y + o.z * o.z + o.w * o.w;
        }
    // deterministic block reduction -> per-(b,tile) partials
#pragma unroll
    for (int off = 16; off; off >>= 1) {
        ls += __shfl_xor_sync(0xFFFFFFFFu, ls, off);
        lq += __shfl_xor_sync(0xFFFFFFFFu, lq, off);
    }
    if ((tid & 31) == 0) { red[tid >> 5] = ls; red[8 + (tid >> 5)] = lq; }
    __syncthreads();
    if (tid == 0) {
        float s = 0.f, q = 0.f;
#pragma unroll
        for (int i = 0; i < 8; ++i) { s += red[i]; q += red[8 + i]; }
        g_psum[b * 8 + tile] = s;
        g_psumsq[b * 8 + tile] = q;
    }
}

// ---------------- K4: per-batch LN stats ------------------------------------------
__global__ void k_stats()
{
    int b = blockIdx.x * blockDim.x + threadIdx.x;
    if (b < Bn) {
        float s = 0.f, q = 0.f;
#pragma unroll
        for (int t = 0; t < 8; ++t) { s += g_psum[b * 8 + t]; q += g_psumsq[b * 8 + t]; }
        float mean = s * (1.0f / 65536.0f);
        float var = q * (1.0f / 65536.0f) - mean * mean;
        g_mean[b] = mean;
        g_rinv[b] = rsqrtf(var + 1e-5f);
    }
}

// ---------------- K5: LayerNorm apply ---------------------------------------------
__global__ __launch_bounds__(256) void k_ln(
    const float* __restrict__ ln_w, const float* __restrict__ ln_b,
    float* __restrict__ out)
{
    size_t i4 = (size_t)blockIdx.x * 256 + threadIdx.x;   // float4 index
    int b = (int)(i4 >> 14);          // 16384 float4 per batch
    int cp = (int)(i4 & 16383);
    float mean = g_mean[b], inv = g_rinv[b];
    float4 r  = reinterpret_cast<const float4*>(g_res)[i4];
    float4 w  = reinterpret_cast<const float4*>(ln_w)[cp];
    float4 lb = reinterpret_cast<const float4*>(ln_b)[cp];
    float4 o;
    o.x = (r.x - mean) * inv * w.x + lb.x;
    o.y = (r.y - mean) * inv * w.y + lb.y;
    o.z = (r.z - mean) * inv * w.z + lb.z;
    o.w = (r.w - mean) * inv * w.w + lb.w;
    reinterpret_cast<float4*>(out)[i4] = o;
}

// ---------------- launch -----------------------------------------------------------
extern "C" void kernel_launch(void* const* d_in, const int* in_sizes, int n_in,
                              void* d_out, int out_size)
{
    (void)in_sizes; (void)n_in; (void)out_size;
    const float* x     = (const float*)d_in[0];
    const float* Wq    = (const float*)d_in[1];
    const float* bq    = (const float*)d_in[2];
    const float* Wk    = (const float*)d_in[3];
    const float* bk    = (const float*)d_in[4];
    const float* Wv    = (const float*)d_in[5];
    const float* bv    = (const float*)d_in[6];
    const float* Wp    = (const float*)d_in[7];
    const float* bp    = (const float*)d_in[8];
    const float* gamma = (const float*)d_in[9];
    const float* temp  = (const float*)d_in[10];
    const float* lnw   = (const float*)d_in[11];
    const float* lnb   = (const float*)d_in[12];
    float* out = (float*)d_out;

    dim3 g1(Bn, 24);
    k_qkv<<<g1, 256>>>(x, Wq, bq, Wk, bk, Wv, bv);
    k_attn<<<Bn * NH, 256>>>(temp);
    dim3 g3(Bn, 8);
    k_proj<<<g3, 256>>>(x, Wp, bp, gamma);
    k_stats<<<1, 1024>>>();
    k_ln<<<65536, 256>>>(lnw, lnb, out);
}

// round 12
// speedup vs baseline: 2.9241x; 2.9241x over previous
#include <cuda_runtime.h>
#include <cstdint>

#define Bn 1024
#define CP 65536          // C * H * W elements per batch image

// ---------------- scratch (device globals; no allocation allowed) ----------------
__device__ __align__(16) float g_qkv[(size_t)3 * Bn * CP];   // [b][w][c][p]
__device__ __align__(16) float g_xt [(size_t)Bn * CP];       // x transposed: [b][p][c]
__device__ __align__(16) float g_aT [(size_t)Bn * CP];       // attn out transposed: [b][p][c]
__device__ __align__(16) float g_res[(size_t)Bn * CP];       // residual output, pre-LN
__device__ float g_psum[Bn * 8];
__device__ float g_psumsq[Bn * 8];
__device__ float g_mean[Bn];
__device__ float g_rinv[Bn];

// ---------------- tf32 mma.sync helpers (base sm_80+ ISA, ok on sm_103) ----------
__device__ __forceinline__ uint32_t f2tf(float f) {
    uint32_t r;
    asm("cvt.rna.tf32.f32 %0, %1;" : "=r"(r) : "f"(f));
    return r;
}
__device__ __forceinline__ void mma8(float* c, const uint32_t* a, const uint32_t* b) {
    asm volatile(
        "mma.sync.aligned.m16n8k8.row.col.f32.tf32.tf32.f32 "
        "{%0,%1,%2,%3}, {%4,%5,%6,%7}, {%8,%9}, {%0,%1,%2,%3};"
        : "+f"(c[0]), "+f"(c[1]), "+f"(c[2]), "+f"(c[3])
        : "r"(a[0]), "r"(a[1]), "r"(a[2]), "r"(a[3]), "r"(b[0]), "r"(b[1]));
}

// ---------------- tf32 tensor-core GEMM core --------------------------------------
// D[128 x 128] = W[128 x 1024] @ B^T where B rows n (0..127): batch g=n>>6, p=n&63,
// B[n][k] = Bbase[g*CP + p*1024 + k]  (K-contiguous activations).
// 256 threads, 8 warps: wm = wid&3 (32 rows), wn = wid>>2 (64 cols).
// Smem: As/Bs [row][k 0..31] uint32 tf32, XOR-swizzled: word = row*32 + (k ^ 4*(row&7)).
__device__ __forceinline__ void gemm_tc(
    const float* __restrict__ Wrow,
    const float* __restrict__ Bbase,
    uint32_t* As, uint32_t* Bs,
    int tid, float (&acc)[2][8][4])
{
    const int lane = tid & 31, wid = tid >> 5;
    const int wm = wid & 3, wn = wid >> 2;
    const int g = lane >> 2, tig = lane & 3;

    int offA[4], offB[4], sw[4];
#pragma unroll
    for (int i = 0; i < 4; ++i) {
        int f = tid + i * 256;
        int row = f >> 3, k4 = f & 7;
        offA[i] = row * 1024 + k4 * 4;
        offB[i] = (row >> 6) * CP + (row & 63) * 1024 + k4 * 4;
        sw[i]   = row * 32 + ((k4 * 4) ^ ((row & 7) << 2));
    }
    float4 ra[4], rb[4];
#pragma unroll
    for (int i = 0; i < 4; ++i) {
        ra[i] = *reinterpret_cast<const float4*>(Wrow + offA[i]);
        rb[i] = *reinterpret_cast<const float4*>(Bbase + offB[i]);
    }

    for (int kc = 0; kc < 1024; kc += 32) {
#pragma unroll
        for (int i = 0; i < 4; ++i) {
            uint4 qa = make_uint4(f2tf(ra[i].x), f2tf(ra[i].y), f2tf(ra[i].z), f2tf(ra[i].w));
            uint4 qb = make_uint4(f2tf(rb[i].x), f2tf(rb[i].y), f2tf(rb[i].z), f2tf(rb[i].w));
            *reinterpret_cast<uint4*>(As + sw[i]) = qa;
            *reinterpret_cast<uint4*>(Bs + sw[i]) = qb;
        }
        __syncthreads();
        if (kc + 32 < 1024) {
#pragma unroll
            for (int i = 0; i < 4; ++i) {
                ra[i] = *reinterpret_cast<const float4*>(Wrow + offA[i] + kc + 32);
                rb[i] = *reinterpret_cast<const float4*>(Bbase + offB[i] + kc + 32);
            }
        }
#pragma unroll
        for (int s = 0; s < 4; ++s) {
            const int k0 = s * 8;
            uint32_t a[2][4], b[8][2];
#pragma unroll
            for (int mt = 0; mt < 2; ++mt) {
                int r0 = wm * 32 + mt * 16 + g;
                int r1 = r0 + 8;
                int s0 = (r0 & 7) << 2;           // (r1&7)==(r0&7)
                a[mt][0] = As[r0 * 32 + ((k0 + tig) ^ s0)];
                a[mt][1] = As[r1 * 32 + ((k0 + tig) ^ s0)];
                a[mt][2] = As[r0 * 32 + ((k0 + tig + 4) ^ s0)];
                a[mt][3] = As[r1 * 32 + ((k0 + tig + 4) ^ s0)];
            }
#pragma unroll
            for (int nt = 0; nt < 8; ++nt) {
                int c = wn * 64 + nt * 8 + g;
                int sc = (c & 7) << 2;
                b[nt][0] = Bs[c * 32 + ((k0 + tig) ^ sc)];
                b[nt][1] = Bs[c * 32 + ((k0 + tig + 4) ^ sc)];
            }
#pragma unroll
            for (int mt = 0; mt < 2; ++mt)
#pragma unroll
                for (int nt = 0; nt < 8; ++nt)
                    mma8(acc[mt][nt], a[mt], b[nt]);
        }
        __syncthreads();
    }
}

// ---------------- K0: transpose x -> xt [b][p][c] ---------------------------------
__global__ __launch_bounds__(256) void k_xt(const float* __restrict__ x)
{
    __shared__ __align__(16) float S[4096];
    const int tid = threadIdx.x;
    const size_t b = blockIdx.y;
    const int c0 = blockIdx.x * 64;
    const float* xb = x + b * CP + (size_t)c0 * 64;
#pragma unroll
    for (int i = 0; i < 4; ++i) {
        int f = tid + i * 256;
        int c = f >> 4, p0 = (f & 15) * 4;
        float4 v = *reinterpret_cast<const float4*>(xb + (size_t)c * 64 + p0);
        S[(p0 + 0) * 64 + (c ^ (((p0 + 0) & 7) * 4))] = v.x;
        S[(p0 + 1) * 64 + (c ^ (((p0 + 1) & 7) * 4))] = v.y;
        S[(p0 + 2) * 64 + (c ^ (((p0 + 2) & 7) * 4))] = v.z;
        S[(p0 + 3) * 64 + (c ^ (((p0 + 3) & 7) * 4))] = v.w;
    }
    __syncthreads();
    float* ot = g_xt + b * CP;
#pragma unroll
    for (int i = 0; i < 4; ++i) {
        int f = tid + i * 256;
        int p = f >> 4, c4 = (f & 15) * 4;
        float4 v = *reinterpret_cast<const float4*>(S + p * 64 + (c4 ^ ((p & 7) * 4)));
        *reinterpret_cast<float4*>(ot + (size_t)p * 1024 + c0 + c4) = v;
    }
}

// ---------------- K1: fused QKV projection (tf32 tensor cores) ---------------------
__global__ __launch_bounds__(256, 1) void k_qkv_mma(
    const float* __restrict__ Wq, const float* __restrict__ bq,
    const float* __restrict__ Wk, const float* __restrict__ bk,
    const float* __restrict__ Wv, const float* __restrict__ bv)
{
    __shared__ __align__(16) uint32_t As[4096];
    __shared__ __align__(16) uint32_t Bs[4096];
    const int tid = threadIdx.x;
    const int bx = blockIdx.x;                 // 0..23
    const int wmat = bx >> 3, tile = bx & 7;
    const int row0 = tile * 128;
    const size_t b0 = (size_t)blockIdx.y * 2;
    const float* W    = (wmat == 0) ? Wq : (wmat == 1) ? Wk : Wv;
    const float* bias = (wmat == 0) ? bq : (wmat == 1) ? bk : bv;

    float acc[2][8][4] = {};
    gemm_tc(W + (size_t)row0 * 1024, g_xt + b0 * CP, As, Bs, tid, acc);

    const int lane = tid & 31, wid = tid >> 5;
    const int wm = wid & 3, wn = wid >> 2;
    const int g = lane >> 2, tig = lane & 3;
#pragma unroll
    for (int mt = 0; mt < 2; ++mt) {
        int r = row0 + wm * 32 + mt * 16 + g;
        float bv0 = bias[r], bv1 = bias[r + 8];
        float* o0 = g_qkv + ((b0 + wn) * 3 + wmat) * CP + (size_t)r * 64;
        float* o1 = o0 + 8 * 64;
#pragma unroll
        for (int nt = 0; nt < 8; ++nt) {
            int p = nt * 8 + 2 * tig;
            *reinterpret_cast<float2*>(o0 + p) =
                make_float2(acc[mt][nt][0] + bv0, acc[mt][nt][1] + bv0);
            *reinterpret_cast<float2*>(o1 + p) =
                make_float2(acc[mt][nt][2] + bv1, acc[mt][nt][3] + bv1);
        }
    }
}

// ---------------- K2: per-(batch, head) attention ----------------------------------
__global__ __launch_bounds__(256) void k_attn(const float* __restrict__ temperature)
{
    __shared__ __align__(16) float S0[4096];
    __shared__ __align__(16) float S1[4096];
    __shared__ __align__(16) float S2[4096];
    const int tid = threadIdx.x;
    const int bh = blockIdx.x;
    const int b = bh >> 4, h = bh & 15;
    const float* qg = g_qkv + ((size_t)b * 3 + 0) * CP + h * 4096;
    const float* kg = g_qkv + ((size_t)b * 3 + 1) * CP + h * 4096;
    const float* vg = g_qkv + ((size_t)b * 3 + 2) * CP + h * 4096;

#pragma unroll
    for (int i = 0; i < 4; ++i) {
        int f = tid + i * 256;
        reinterpret_cast<float4*>(S0)[f] = reinterpret_cast<const float4*>(qg)[f];
        reinterpret_cast<float4*>(S1)[f] = reinterpret_cast<const float4*>(kg)[f];
    }
    __syncthreads();

    if (tid < 128) {
        float* mat = (tid < 64) ? S0 : S1;
        int r = tid & 63;
        float s = 0.f;
        for (int i = 0; i < 64; ++i) { int p = (i + r) & 63; float v = mat[r * 64 + p]; s = fmaf(v, v, s); }
        float inv = 1.0f / fmaxf(sqrtf(s), 1e-12f);
        for (int i = 0; i < 64; ++i) { int p = (i + r) & 63; mat[r * 64 + p] *= inv; }
    }
    __syncthreads();

    const float invT = 1.0f / (temperature[0] + 1e-6f);
    const int tx = tid & 15, ty = tid >> 4;

    {
        float a[4][4] = {};
        const int n0 = tx * 4, m0 = ty * 4;
#pragma unroll 8
        for (int d = 0; d < 64; ++d) {
            float4 kf = *reinterpret_cast<const float4*>(S1 + d * 64 + m0);
            float4 qf = *reinterpret_cast<const float4*>(S0 + d * 64 + n0);
            float kv[4] = {kf.x, kf.y, kf.z, kf.w};
            float qv[4] = {qf.x, qf.y, qf.z, qf.w};
#pragma unroll
            for (int i = 0; i < 4; ++i)
#pragma unroll
                for (int j = 0; j < 4; ++j)
                    a[i][j] = fmaf(kv[i], qv[j], a[i][j]);
        }
#pragma unroll
        for (int i = 0; i < 4; ++i)
            *reinterpret_cast<float4*>(S2 + (m0 + i) * 64 + n0) =
                make_float4(a[i][0] * invT, a[i][1] * invT, a[i][2] * invT, a[i][3] * invT);
    }
    __syncthreads();

    {
        const int n = tid & 63, sub = tid >> 6;
        float mx = -1e30f;
#pragma unroll
        for (int i = 0; i < 16; ++i) mx = fmaxf(mx, S2[(sub * 16 + i) * 64 + n]);
        S0[sub * 64 + n] = mx;
        __syncthreads();
        float gmx = fmaxf(fmaxf(S0[n], S0[64 + n]), fmaxf(S0[128 + n], S0[192 + n]));
        __syncthreads();
        float s = 0.f;
#pragma unroll
        for (int i = 0; i < 16; ++i) {
            float e = __expf(S2[(sub * 16 + i) * 64 + n] - gmx);
            S2[(sub * 16 + i) * 64 + n] = e;
            s += e;
        }
        S0[sub * 64 + n] = s;
        __syncthreads();
        float inv = 1.0f / (S0[n] + S0[64 + n] + S0[128 + n] + S0[192 + n]);
#pragma unroll
        for (int i = 0; i < 16; ++i) S2[(sub * 16 + i) * 64 + n] *= inv;
    }
    __syncthreads();

    // V transposed + swizzled into S0
#pragma unroll
    for (int i = 0; i < 4; ++i) {
        int f = tid + i * 256;
        int d = f >> 4, p4 = (f & 15) * 4;
        float4 vv = reinterpret_cast<const float4*>(vg)[f];
        S0[(p4 + 0) * 64 + (d ^ (((p4 + 0) & 7) * 4))] = vv.x;
        S0[(p4 + 1) * 64 + (d ^ (((p4 + 1) & 7) * 4))] = vv.y;
        S0[(p4 + 2) * 64 + (d ^ (((p4 + 2) & 7) * 4))] = vv.z;
        S0[(p4 + 3) * 64 + (d ^ (((p4 + 3) & 7) * 4))] = vv.w;
    }
    __syncthreads();

    // out[d][n] = sum_m v[d][m] * attn^T[m][n]; stage transposed into S1
    {
        const int n0 = tx * 4, d0 = ty * 4;
        float o[4][4] = {};
#pragma unroll 8
        for (int m = 0; m < 64; ++m) {
            float4 vf = *reinterpret_cast<const float4*>(S0 + m * 64 + (d0 ^ ((m & 7) * 4)));
            float4 af = *reinterpret_cast<const float4*>(S2 + m * 64 + n0);
            float vv[4] = {vf.x, vf.y, vf.z, vf.w};
            float aa[4] = {af.x, af.y, af.z, af.w};
#pragma unroll
            for (int i = 0; i < 4; ++i)
#pragma unroll
                for (int j = 0; j < 4; ++j)
                    o[i][j] = fmaf(vv[i], aa[j], o[i][j]);
        }
#pragma unroll
        for (int i = 0; i < 4; ++i)
#pragma unroll
            for (int j = 0; j < 4; ++j)
                S1[(n0 + j) * 64 + (d0 + i)] = o[i][j];
    }
    __syncthreads();
    // write transposed output: g_aT[b][p][h*64 + d]
    float* og = g_aT + (size_t)b * CP + h * 64;
#pragma unroll
    for (int i = 0; i < 4; ++i) {
        int f = tid + i * 256;
        int p = f >> 4, d4 = (f & 15) * 4;
        float4 v = *reinterpret_cast<const float4*>(S1 + p * 64 + d4);
        *reinterpret_cast<float4*>(og + (size_t)p * 1024 + d4) = v;
    }
}

// ---------------- K3: output projection + residual + LN partials (tf32 MMA) --------
__global__ __launch_bounds__(256, 1) void k_proj_mma(
    const float* __restrict__ x,
    const float* __restrict__ Wp, const float* __restrict__ bp,
    const float* __restrict__ gamma)
{
    __shared__ __align__(16) uint32_t As[4096];
    __shared__ __align__(16) uint32_t Bs[4096];
    __shared__ float red[16];
    const int tid = threadIdx.x;
    const int tile = blockIdx.x;               // 0..7
    const int row0 = tile * 128;
    const size_t b0 = (size_t)blockIdx.y * 2;

    float acc[2][8][4] = {};
    gemm_tc(Wp + (size_t)row0 * 1024, g_aT + b0 * CP, As, Bs, tid, acc);

    const int lane = tid & 31, wid = tid >> 5;
    const int wm = wid & 3, wn = wid >> 2;
    const int g = lane >> 2, tig = lane & 3;
    const float gam = gamma[0];
    const float g1 = 1.0f - gam;
    float ls = 0.f, lq = 0.f;
#pragma unroll
    for (int mt = 0; mt < 2; ++mt) {
        int r = row0 + wm * 32 + mt * 16 + g;
        float bb0 = bp[r], bb1 = bp[r + 8];
        size_t base = (b0 + wn) * CP + (size_t)r * 64;
#pragma unroll
        for (int nt = 0; nt < 8; ++nt) {
            int p = nt * 8 + 2 * tig;
            float2 x0 = *reinterpret_cast<const float2*>(x + base + p);
            float2 x1 = *reinterpret_cast<const float2*>(x + base + 8 * 64 + p);
            float2 v0, v1;
            v0.x = gam * (acc[mt][nt][0] + bb0) + g1 * x0.x;
            v0.y = gam * (acc[mt][nt][1] + bb0) + g1 * x0.y;
            v1.x = gam * (acc[mt][nt][2] + bb1) + g1 * x1.x;
            v1.y = gam * (acc[mt][nt][3] + bb1) + g1 * x1.y;
            *reinterpret_cast<float2*>(g_res + base + p) = v0;
            *reinterpret_cast<float2*>(g_res + base + 8 * 64 + p) = v1;
            ls += v0.x + v0.y + v1.x + v1.y;
            lq += v0.x * v0.x + v0.y * v0.y + v1.x * v1.x + v1.y * v1.y;
        }
    }
#pragma unroll
    for (int off = 16; off; off >>= 1) {
        ls += __shfl_xor_sync(0xFFFFFFFFu, ls, off);
        lq += __shfl_xor_sync(0xFFFFFFFFu, lq, off);
    }
    if (lane == 0) { red[wid * 2] = ls; red[wid * 2 + 1] = lq; }
    __syncthreads();
    if (tid == 0) {
        float s0 = 0.f, q0 = 0.f, s1 = 0.f, q1 = 0.f;
#pragma unroll
        for (int w = 0; w < 4; ++w) {
            s0 += red[w * 2];     q0 += red[w * 2 + 1];
            s1 += red[8 + w * 2]; q1 += red[8 + w * 2 + 1];
        }
        g_psum[(b0 + 0) * 8 + tile] = s0; g_psumsq[(b0 + 0) * 8 + tile] = q0;
        g_psum[(b0 + 1) * 8 + tile] = s1; g_psumsq[(b0 + 1) * 8 + tile] = q1;
    }
}

// ---------------- K4: per-batch LN stats ------------------------------------------
__global__ void k_stats()
{
    int b = blockIdx.x * blockDim.x + threadIdx.x;
    if (b < Bn) {
        float s = 0.f, q = 0.f;
#pragma unroll
        for (int t = 0; t < 8; ++t) { s += g_psum[b * 8 + t]; q += g_psumsq[b * 8 + t]; }
        float mean = s * (1.0f / 65536.0f);
        float var = q * (1.0f / 65536.0f) - mean * mean;
        g_mean[b] = mean;
        g_rinv[b] = rsqrtf(var + 1e-5f);
    }
}

// ---------------- K5: LayerNorm apply ---------------------------------------------
__global__ __launch_bounds__(256) void k_ln(
    const float* __restrict__ ln_w, const float* __restrict__ ln_b,
    float* __restrict__ out)
{
    size_t i4 = (size_t)blockIdx.x * 256 + threadIdx.x;
    int b = (int)(i4 >> 14);
    int cp = (int)(i4 & 16383);
    float mean = g_mean[b], inv = g_rinv[b];
    float4 r  = reinterpret_cast<const float4*>(g_res)[i4];
    float4 w  = reinterpret_cast<const float4*>(ln_w)[cp];
    float4 lb = reinterpret_cast<const float4*>(ln_b)[cp];
    float4 o;
    o.x = (r.x - mean) * inv * w.x + lb.x;
    o.y = (r.y - mean) * inv * w.y + lb.y;
    o.z = (r.z - mean) * inv * w.z + lb.z;
    o.w = (r.w - mean) * inv * w.w + lb.w;
    reinterpret_cast<float4*>(out)[i4] = o;
}

// ---------------- launch -----------------------------------------------------------
extern "C" void kernel_launch(void* const* d_in, const int* in_sizes, int n_in,
                              void* d_out, int out_size)
{
    (void)in_sizes; (void)n_in; (void)out_size;
    const float* x     = (const float*)d_in[0];
    const float* Wq    = (const float*)d_in[1];
    const float* bq    = (const float*)d_in[2];
    const float* Wk    = (const float*)d_in[3];
    const float* bk    = (const float*)d_in[4];
    const float* Wv    = (const float*)d_in[5];
    const float* bv    = (const float*)d_in[6];
    const float* Wp    = (const float*)d_in[7];
    const float* bp    = (const float*)d_in[8];
    const float* gamma = (const float*)d_in[9];
    const float* temp  = (const float*)d_in[10];
    const float* lnw   = (const float*)d_in[11];
    const float* lnb   = (const float*)d_in[12];
    float* out = (float*)d_out;

    dim3 gx(16, Bn);
    k_xt<<<gx, 256>>>(x);
    dim3 g1(24, Bn / 2);
    k_qkv_mma<<<g1, 256>>>(Wq, bq, Wk, bk, Wv, bv);
    k_attn<<<Bn * 16, 256>>>(temp);
    dim3 g3(8, Bn / 2);
    k_proj_mma<<<g3, 256>>>(x, Wp, bp, gamma);
    k_stats<<<1, 1024>>>();
    k_ln<<<65536, 256>>>(lnw, lnb, out);
}

// round 16
// speedup vs baseline: 3.1449x; 1.0755x over previous
#include <cuda_runtime.h>
#include <cstdint>

#define Bn 1024
#define CP 65536          // C * H * W elements per batch image

// ---------------- scratch (device globals; no allocation allowed) ----------------
__device__ __align__(16) float g_qkv[(size_t)3 * Bn * CP];   // [b][w][c][p] fp32
__device__ __align__(16) float g_xt [(size_t)Bn * CP];       // x transposed [b][p][c], tf32-rounded
__device__ __align__(16) float g_aT [(size_t)Bn * CP];       // attn out transposed, tf32-rounded
__device__ __align__(16) float g_res[(size_t)Bn * CP];       // residual output, pre-LN
__device__ __align__(16) float g_wtf[(size_t)4 * 1024 * 1024]; // weights tf32-rounded: q,k,v,p
__device__ float g_psum[Bn * 8];
__device__ float g_psumsq[Bn * 8];
__device__ float g_mean[Bn];
__device__ float g_rinv[Bn];

// ---------------- helpers ----------------------------------------------------------
__device__ __forceinline__ uint32_t smem_u32(const void* p) {
    uint32_t a;
    asm("{ .reg .u64 t; cvta.to.shared.u64 t, %1; cvt.u32.u64 %0, t; }" : "=r"(a) : "l"(p));
    return a;
}
__device__ __forceinline__ uint32_t f2tf(float f) {
    uint32_t r;
    asm("cvt.rna.tf32.f32 %0, %1;" : "=r"(r) : "f"(f));
    return r;
}
__device__ __forceinline__ float f2tff(float f) { return __uint_as_float(f2tf(f)); }
__device__ __forceinline__ void mma8(float* c, const uint32_t* a, const uint32_t* b) {
    asm volatile(
        "mma.sync.aligned.m16n8k8.row.col.f32.tf32.tf32.f32 "
        "{%0,%1,%2,%3}, {%4,%5,%6,%7}, {%8,%9}, {%0,%1,%2,%3};"
        : "+f"(c[0]), "+f"(c[1]), "+f"(c[2]), "+f"(c[3])
        : "r"(a[0]), "r"(a[1]), "r"(a[2]), "r"(a[3]), "r"(b[0]), "r"(b[1]));
}
__device__ __forceinline__ void cpa16(uint32_t dst, const float* src) {
    asm volatile("cp.async.cg.shared.global [%0], [%1], 16;" :: "r"(dst), "l"(src) : "memory");
}
#define CP_COMMIT() asm volatile("cp.async.commit_group;" ::: "memory")

// ---------------- pipelined tf32 tensor-core GEMM core -----------------------------
// D[128 x 128] = Wtf[128 x 1024] @ B^T, B rows n: g=n>>6, p=n&63,
// B[n][k] = Btf[g*CP + p*1024 + k]  (pre-converted tf32 activations).
// BK=16, 2-stage cp.async pipeline. Smem rows padded to 20 words (conflict-free).
// Stage: A 128x20 words, B 128x20 words -> 5120 words; 2 stages = 40KB.
__device__ __forceinline__ void gemm_pipe(
    const float* __restrict__ Wtf,
    const float* __restrict__ Btf,
    uint32_t* SM, int tid, float (&acc)[2][8][4])
{
    const int lane = tid & 31, wid = tid >> 5;
    const int wm = wid & 3, wn = wid >> 2;
    const int g = lane >> 2, tig = lane & 3;
    const uint32_t smb = smem_u32(SM);

    int gA[2], gB[2];
    uint32_t dA[2], dB[2];
#pragma unroll
    for (int i = 0; i < 2; ++i) {
        int f = tid + i * 256;
        int row = f >> 2, k4 = f & 3;          // 128 rows x 4 16B-chunks
        gA[i] = row * 1024 + k4 * 4;
        gB[i] = (row >> 6) * CP + (row & 63) * 1024 + k4 * 4;
        dA[i] = (uint32_t)(row * 20 + k4 * 4) * 4;
        dB[i] = dA[i] + 2560 * 4;
    }
    // prologue: stage 0
#pragma unroll
    for (int i = 0; i < 2; ++i) {
        cpa16(smb + dA[i], Wtf + gA[i]);
        cpa16(smb + dB[i], Btf + gB[i]);
    }
    CP_COMMIT();

    for (int c = 0; c < 64; ++c) {
        if (c < 63) {
            uint32_t sb = smb + (uint32_t)(((c + 1) & 1) * 20480);
            int kc = (c + 1) * 16;
#pragma unroll
            for (int i = 0; i < 2; ++i) {
                cpa16(sb + dA[i], Wtf + gA[i] + kc);
                cpa16(sb + dB[i], Btf + gB[i] + kc);
            }
            CP_COMMIT();
            asm volatile("cp.async.wait_group 1;" ::: "memory");
        } else {
            asm volatile("cp.async.wait_group 0;" ::: "memory");
        }
        __syncthreads();
        const uint32_t* As = SM + (c & 1) * 5120;
        const uint32_t* Bs = As + 2560;
#pragma unroll
        for (int s = 0; s < 2; ++s) {
            const int k0 = s * 8;
            uint32_t a[2][4], b[8][2];
#pragma unroll
            for (int mt = 0; mt < 2; ++mt) {
                int r0 = wm * 32 + mt * 16 + g;
                a[mt][0] = As[r0 * 20 + k0 + tig];
                a[mt][1] = As[(r0 + 8) * 20 + k0 + tig];
                a[mt][2] = As[r0 * 20 + k0 + tig + 4];
                a[mt][3] = As[(r0 + 8) * 20 + k0 + tig + 4];
            }
#pragma unroll
            for (int nt = 0; nt < 8; ++nt) {
                int cc = wn * 64 + nt * 8 + g;
                b[nt][0] = Bs[cc * 20 + k0 + tig];
                b[nt][1] = Bs[cc * 20 + k0 + tig + 4];
            }
#pragma unroll
            for (int mt = 0; mt < 2; ++mt)
#pragma unroll
                for (int nt = 0; nt < 8; ++nt)
                    mma8(acc[mt][nt], a[mt], b[nt]);
        }
        __syncthreads();
    }
}

// ---------------- K-1: convert weights to tf32 -------------------------------------
__global__ __launch_bounds__(256) void k_wcvt(
    const float* __restrict__ Wq, const float* __restrict__ Wk,
    const float* __restrict__ Wv, const float* __restrict__ Wp)
{
    const float* src = (blockIdx.y == 0) ? Wq : (blockIdx.y == 1) ? Wk
                     : (blockIdx.y == 2) ? Wv : Wp;
    size_t i4 = (size_t)blockIdx.x * 256 + threadIdx.x;
    float4 v = reinterpret_cast<const float4*>(src)[i4];
    uint4 o = make_uint4(f2tf(v.x), f2tf(v.y), f2tf(v.z), f2tf(v.w));
    reinterpret_cast<uint4*>(g_wtf + (size_t)blockIdx.y * 1048576)[i4] = o;
}

// ---------------- K0: transpose x -> xt [b][p][c] (tf32-rounded) -------------------
__global__ __launch_bounds__(256) void k_xt(const float* __restrict__ x)
{
    __shared__ __align__(16) float S[4096];
    const int tid = threadIdx.x;
    const size_t b = blockIdx.y;
    const int c0 = blockIdx.x * 64;
    const float* xb = x + b * CP + (size_t)c0 * 64;
#pragma unroll
    for (int i = 0; i < 4; ++i) {
        int f = tid + i * 256;
        int c = f >> 4, p0 = (f & 15) * 4;
        float4 v = *reinterpret_cast<const float4*>(xb + (size_t)c * 64 + p0);
        S[(p0 + 0) * 64 + (c ^ (((p0 + 0) & 7) * 4))] = v.x;
        S[(p0 + 1) * 64 + (c ^ (((p0 + 1) & 7) * 4))] = v.y;
        S[(p0 + 2) * 64 + (c ^ (((p0 + 2) & 7) * 4))] = v.z;
        S[(p0 + 3) * 64 + (c ^ (((p0 + 3) & 7) * 4))] = v.w;
    }
    __syncthreads();
    float* ot = g_xt + b * CP;
#pragma unroll
    for (int i = 0; i < 4; ++i) {
        int f = tid + i * 256;
        int p = f >> 4, c4 = (f & 15) * 4;
        float4 v = *reinterpret_cast<const float4*>(S + p * 64 + (c4 ^ ((p & 7) * 4)));
        float4 o = make_float4(f2tff(v.x), f2tff(v.y), f2tff(v.z), f2tff(v.w));
        *reinterpret_cast<float4*>(ot + (size_t)p * 1024 + c0 + c4) = o;
    }
}

// ---------------- K1: fused QKV projection (tf32 tensor cores, pipelined) ----------
__global__ __launch_bounds__(256, 2) void k_qkv_mma(
    const float* __restrict__ bq, const float* __restrict__ bk,
    const float* __restrict__ bv)
{
    __shared__ __align__(16) uint32_t SM[10240];
    const int tid = threadIdx.x;
    const int bx = blockIdx.x;                 // 0..23
    const int wmat = bx >> 3, tile = bx & 7;
    const int row0 = tile * 128;
    const size_t b0 = (size_t)blockIdx.y * 2;
    const float* bias = (wmat == 0) ? bq : (wmat == 1) ? bk : bv;

    float acc[2][8][4] = {};
    gemm_pipe(g_wtf + (size_t)wmat * 1048576 + (size_t)row0 * 1024,
              g_xt + b0 * CP, SM, tid, acc);

    const int lane = tid & 31, wid = tid >> 5;
    const int wm = wid & 3, wn = wid >> 2;
    const int g = lane >> 2, tig = lane & 3;
#pragma unroll
    for (int mt = 0; mt < 2; ++mt) {
        int r = row0 + wm * 32 + mt * 16 + g;
        float bv0 = bias[r], bv1 = bias[r + 8];
        float* o0 = g_qkv + ((b0 + wn) * 3 + wmat) * CP + (size_t)r * 64;
        float* o1 = o0 + 8 * 64;
#pragma unroll
        for (int nt = 0; nt < 8; ++nt) {
            int p = nt * 8 + 2 * tig;
            *reinterpret_cast<float2*>(o0 + p) =
                make_float2(acc[mt][nt][0] + bv0, acc[mt][nt][1] + bv0);
            *reinterpret_cast<float2*>(o1 + p) =
                make_float2(acc[mt][nt][2] + bv1, acc[mt][nt][3] + bv1);
        }
    }
}

// ---------------- K2: per-(batch, head) attention ----------------------------------
__global__ __launch_bounds__(256) void k_attn(const float* __restrict__ temperature)
{
    __shared__ __align__(16) float S0[4096];
    __shared__ __align__(16) float S1[4096];
    __shared__ __align__(16) float S2[4096];
    const int tid = threadIdx.x;
    const int bh = blockIdx.x;
    const int b = bh >> 4, h = bh & 15;
    const float* qg = g_qkv + ((size_t)b * 3 + 0) * CP + h * 4096;
    const float* kg = g_qkv + ((size_t)b * 3 + 1) * CP + h * 4096;
    const float* vg = g_qkv + ((size_t)b * 3 + 2) * CP + h * 4096;

#pragma unroll
    for (int i = 0; i < 4; ++i) {
        int f = tid + i * 256;
        reinterpret_cast<float4*>(S0)[f] = reinterpret_cast<const float4*>(qg)[f];
        reinterpret_cast<float4*>(S1)[f] = reinterpret_cast<const float4*>(kg)[f];
    }
    __syncthreads();

    if (tid < 128) {
        float* mat = (tid < 64) ? S0 : S1;
        int r = tid & 63;
        float s = 0.f;
        for (int i = 0; i < 64; ++i) { int p = (i + r) & 63; float v = mat[r * 64 + p]; s = fmaf(v, v, s); }
        float inv = 1.0f / fmaxf(sqrtf(s), 1e-12f);
        for (int i = 0; i < 64; ++i) { int p = (i + r) & 63; mat[r * 64 + p] *= inv; }
    }
    __syncthreads();

    const float invT = 1.0f / (temperature[0] + 1e-6f);
    const int tx = tid & 15, ty = tid >> 4;

    {
        float a[4][4] = {};
        const int n0 = tx * 4, m0 = ty * 4;
#pragma unroll 8
        for (int d = 0; d < 64; ++d) {
            float4 kf = *reinterpret_cast<const float4*>(S1 + d * 64 + m0);
            float4 qf = *reinterpret_cast<const float4*>(S0 + d * 64 + n0);
            float kv[4] = {kf.x, kf.y, kf.z, kf.w};
            float qv[4] = {qf.x, qf.y, qf.z, qf.w};
#pragma unroll
            for (int i = 0; i < 4; ++i)
#pragma unroll
                for (int j = 0; j < 4; ++j)
                    a[i][j] = fmaf(kv[i], qv[j], a[i][j]);
        }
#pragma unroll
        for (int i = 0; i < 4; ++i)
            *reinterpret_cast<float4*>(S2 + (m0 + i) * 64 + n0) =
                make_float4(a[i][0] * invT, a[i][1] * invT, a[i][2] * invT, a[i][3] * invT);
    }
    __syncthreads();

    {
        const int n = tid & 63, sub = tid >> 6;
        float mx = -1e30f;
#pragma unroll
        for (int i = 0; i < 16; ++i) mx = fmaxf(mx, S2[(sub * 16 + i) * 64 + n]);
        S0[sub * 64 + n] = mx;
        __syncthreads();
        float gmx = fmaxf(fmaxf(S0[n], S0[64 + n]), fmaxf(S0[128 + n], S0[192 + n]));
        __syncthreads();
        float s = 0.f;
#pragma unroll
        for (int i = 0; i < 16; ++i) {
            float e = __expf(S2[(sub * 16 + i) * 64 + n] - gmx);
            S2[(sub * 16 + i) * 64 + n] = e;
            s += e;
        }
        S0[sub * 64 + n] = s;
        __syncthreads();
        float inv = 1.0f / (S0[n] + S0[64 + n] + S0[128 + n] + S0[192 + n]);
#pragma unroll
        for (int i = 0; i < 16; ++i) S2[(sub * 16 + i) * 64 + n] *= inv;
    }
    __syncthreads();

    // V transposed + swizzled into S0
#pragma unroll
    for (int i = 0; i < 4; ++i) {
        int f = tid + i * 256;
        int d = f >> 4, p4 = (f & 15) * 4;
        float4 vv = reinterpret_cast<const float4*>(vg)[f];
        S0[(p4 + 0) * 64 + (d ^ (((p4 + 0) & 7) * 4))] = vv.x;
        S0[(p4 + 1) * 64 + (d ^ (((p4 + 1) & 7) * 4))] = vv.y;
        S0[(p4 + 2) * 64 + (d ^ (((p4 + 2) & 7) * 4))] = vv.z;
        S0[(p4 + 3) * 64 + (d ^ (((p4 + 3) & 7) * 4))] = vv.w;
    }
    __syncthreads();

    // out[d][n] = sum_m v[d][m] * attn^T[m][n]; stage transposed into S1
    {
        const int n0 = tx * 4, d0 = ty * 4;
        float o[4][4] = {};
#pragma unroll 8
        for (int m = 0; m < 64; ++m) {
            float4 vf = *reinterpret_cast<const float4*>(S0 + m * 64 + (d0 ^ ((m & 7) * 4)));
            float4 af = *reinterpret_cast<const float4*>(S2 + m * 64 + n0);
            float vv[4] = {vf.x, vf.y, vf.z, vf.w};
            float aa[4] = {af.x, af.y, af.z, af.w};
#pragma unroll
            for (int i = 0; i < 4; ++i)
#pragma unroll
                for (int j = 0; j < 4; ++j)
                    o[i][j] = fmaf(vv[i], aa[j], o[i][j]);
        }
#pragma unroll
        for (int i = 0; i < 4; ++i)
#pragma unroll
            for (int j = 0; j < 4; ++j)
                S1[(n0 + j) * 64 + (d0 + i)] = o[i][j];
    }
    __syncthreads();
    // write transposed output (tf32-rounded): g_aT[b][p][h*64 + d]
    float* og = g_aT + (size_t)b * CP + h * 64;
#pragma unroll
    for (int i = 0; i < 4; ++i) {
        int f = tid + i * 256;
        int p = f >> 4, d4 = (f & 15) * 4;
        float4 v = *reinterpret_cast<const float4*>(S1 + p * 64 + d4);
        float4 o = make_float4(f2tff(v.x), f2tff(v.y), f2tff(v.z), f2tff(v.w));
        *reinterpret_cast<float4*>(og + (size_t)p * 1024 + d4) = o;
    }
}

// ---------------- K3: output projection + residual + LN partials -------------------
__global__ __launch_bounds__(256, 2) void k_proj_mma(
    const float* __restrict__ x,
    const float* __restrict__ bp, const float* __restrict__ gamma)
{
    __shared__ __align__(16) uint32_t SM[10240];
    __shared__ float red[16];
    const int tid = threadIdx.x;
    const int tile = blockIdx.x;               // 0..7
    const int row0 = tile * 128;
    const size_t b0 = (size_t)blockIdx.y * 2;

    float acc[2][8][4] = {};
    gemm_pipe(g_wtf + (size_t)3 * 1048576 + (size_t)row0 * 1024,
              g_aT + b0 * CP, SM, tid, acc);

    const int lane = tid & 31, wid = tid >> 5;
    const int wm = wid & 3, wn = wid >> 2;
    const int g = lane >> 2, tig = lane & 3;
    const float gam = gamma[0];
    const float g1 = 1.0f - gam;
    float ls = 0.f, lq = 0.f;
#pragma unroll
    for (int mt = 0; mt < 2; ++mt) {
        int r = row0 + wm * 32 + mt * 16 + g;
        float bb0 = bp[r], bb1 = bp[r + 8];
        size_t base = (b0 + wn) * CP + (size_t)r * 64;
#pragma unroll
        for (int nt = 0; nt < 8; ++nt) {
            int p = nt * 8 + 2 * tig;
            float2 x0 = *reinterpret_cast<const float2*>(x + base + p);
            float2 x1 = *reinterpret_cast<const float2*>(x + base + 8 * 64 + p);
            float2 v0, v1;
            v0.x = gam * (acc[mt][nt][0] + bb0) + g1 * x0.x;
            v0.y = gam * (acc[mt][nt][1] + bb0) + g1 * x0.y;
            v1.x = gam * (acc[mt][nt][2] + bb1) + g1 * x1.x;
            v1.y = gam * (acc[mt][nt][3] + bb1) + g1 * x1.y;
            *reinterpret_cast<float2*>(g_res + base + p) = v0;
            *reinterpret_cast<float2*>(g_res + base + 8 * 64 + p) = v1;
            ls += v0.x + v0.y + v1.x + v1.y;
            lq += v0.x * v0.x + v0.y * v0.y + v1.x * v1.x + v1.y * v1.y;
        }
    }
#pragma unroll
    for (int off = 16; off; off >>= 1) {
        ls += __shfl_xor_sync(0xFFFFFFFFu, ls, off);
        lq += __shfl_xor_sync(0xFFFFFFFFu, lq, off);
    }
    if (lane == 0) { red[wid * 2] = ls; red[wid * 2 + 1] = lq; }
    __syncthreads();
    if (tid == 0) {
        float s0 = 0.f, q0 = 0.f, s1 = 0.f, q1 = 0.f;
#pragma unroll
        for (int w = 0; w < 4; ++w) {
            s0 += red[w * 2];     q0 += red[w * 2 + 1];
            s1 += red[8 + w * 2]; q1 += red[8 + w * 2 + 1];
        }
        g_psum[(b0 + 0) * 8 + tile] = s0; g_psumsq[(b0 + 0) * 8 + tile] = q0;
        g_psum[(b0 + 1) * 8 + tile] = s1; g_psumsq[(b0 + 1) * 8 + tile] = q1;
    }
}

// ---------------- K4: per-batch LN stats ------------------------------------------
__global__ void k_stats()
{
    int b = blockIdx.x * blockDim.x + threadIdx.x;
    if (b < Bn) {
        float s = 0.f, q = 0.f;
#pragma unroll
        for (int t = 0; t < 8; ++t) { s += g_psum[b * 8 + t]; q += g_psumsq[b * 8 + t]; }
        float mean = s * (1.0f / 65536.0f);
        float var = q * (1.0f / 65536.0f) - mean * mean;
        g_mean[b] = mean;
        g_rinv[b] = rsqrtf(var + 1e-5f);
    }
}

// ---------------- K5: LayerNorm apply ---------------------------------------------
__global__ __launch_bounds__(256) void k_ln(
    const float* __restrict__ ln_w, const float* __restrict__ ln_b,
    float* __restrict__ out)
{
    size_t i4 = (size_t)blockIdx.x * 256 + threadIdx.x;
    int b = (int)(i4 >> 14);
    int cp = (int)(i4 & 16383);
    float mean = g_mean[b], inv = g_rinv[b];
    float4 r  = reinterpret_cast<const float4*>(g_res)[i4];
    float4 w  = reinterpret_cast<const float4*>(ln_w)[cp];
    float4 lb = reinterpret_cast<const float4*>(ln_b)[cp];
    float4 o;
    o.x = (r.x - mean) * inv * w.x + lb.x;
    o.y = (r.y - mean) * inv * w.y + lb.y;
    o.z = (r.z - mean) * inv * w.z + lb.z;
    o.w = (r.w - mean) * inv * w.w + lb.w;
    reinterpret_cast<float4*>(out)[i4] = o;
}

// ---------------- launch -----------------------------------------------------------
extern "C" void kernel_launch(void* const* d_in, const int* in_sizes, int n_in,
                              void* d_out, int out_size)
{
    (void)in_sizes; (void)n_in; (void)out_size;
    const float* x     = (const float*)d_in[0];
    const float* Wq    = (const float*)d_in[1];
    const float* bq    = (const float*)d_in[2];
    const float* Wk    = (const float*)d_in[3];
    const float* bk    = (const float*)d_in[4];
    const float* Wv    = (const float*)d_in[5];
    const float* bv    = (const float*)d_in[6];
    const float* Wp    = (const float*)d_in[7];
    const float* bp    = (const float*)d_in[8];
    const float* gamma = (const float*)d_in[9];
    const float* temp  = (const float*)d_in[10];
    const float* lnw   = (const float*)d_in[11];
    const float* lnb   = (const float*)d_in[12];
    float* out = (float*)d_out;

    dim3 gw(1024, 4);
    k_wcvt<<<gw, 256>>>(Wq, Wk, Wv, Wp);
    dim3 gx(16, Bn);
    k_xt<<<gx, 256>>>(x);
    dim3 g1(24, Bn / 2);
    k_qkv_mma<<<g1, 256>>>(bq, bk, bv);
    k_attn<<<Bn * 16, 256>>>(temp);
    dim3 g3(8, Bn / 2);
    k_proj_mma<<<g3, 256>>>(x, bp, gamma);
    k_stats<<<1, 1024>>>();
    k_ln<<<65536, 256>>>(lnw, lnb, out);
}

// round 17
// speedup vs baseline: 3.6609x; 1.1641x over previous
#include <cuda_runtime.h>
#include <cstdint>

#define Bn 1024
#define CP 65536          // C * H * W elements per batch image

// ---------------- scratch (device globals; no allocation allowed) ----------------
__device__ __align__(16) float g_qkv[(size_t)3 * Bn * CP];   // [b][w][c][p] fp32
__device__ __align__(16) float g_xt [(size_t)Bn * CP];       // x transposed [b][p][c], tf32-rounded
__device__ __align__(16) float g_aT [(size_t)Bn * CP];       // attn out transposed, tf32-rounded
__device__ __align__(16) float g_res[(size_t)Bn * CP];       // residual output, pre-LN
__device__ __align__(16) float g_wtf[(size_t)4 * 1024 * 1024]; // weights tf32-rounded: q,k,v,p
__device__ float g_psum[Bn * 8];
__device__ float g_psumsq[Bn * 8];
__device__ float g_mean[Bn];
__device__ float g_rinv[Bn];

// ---------------- helpers ----------------------------------------------------------
__device__ __forceinline__ uint32_t smem_u32(const void* p) {
    uint32_t a;
    asm("{ .reg .u64 t; cvta.to.shared.u64 t, %1; cvt.u32.u64 %0, t; }" : "=r"(a) : "l"(p));
    return a;
}
__device__ __forceinline__ uint32_t f2tf(float f) {
    uint32_t r;
    asm("cvt.rna.tf32.f32 %0, %1;" : "=r"(r) : "f"(f));
    return r;
}
__device__ __forceinline__ float f2tff(float f) { return __uint_as_float(f2tf(f)); }
__device__ __forceinline__ void mma8(float* c, const uint32_t* a, const uint32_t* b) {
    asm volatile(
        "mma.sync.aligned.m16n8k8.row.col.f32.tf32.tf32.f32 "
        "{%0,%1,%2,%3}, {%4,%5,%6,%7}, {%8,%9}, {%0,%1,%2,%3};"
        : "+f"(c[0]), "+f"(c[1]), "+f"(c[2]), "+f"(c[3])
        : "r"(a[0]), "r"(a[1]), "r"(a[2]), "r"(a[3]), "r"(b[0]), "r"(b[1]));
}
__device__ __forceinline__ void cpa16(uint32_t dst, const float* src) {
    asm volatile("cp.async.cg.shared.global [%0], [%1], 16;" :: "r"(dst), "l"(src) : "memory");
}
#define CP_COMMIT() asm volatile("cp.async.commit_group;" ::: "memory")

// ---------------- pipelined tf32 tensor-core GEMM core -----------------------------
// D[128 x 128] = Wtf[128 x 1024] @ B^T, B rows n: g=n>>6, p=n&63,
// B[n][k] = Btf[g*CP + p*1024 + k]  (pre-converted tf32 activations).
// BK=32, 3-stage cp.async pipeline. Rows padded to 36 words (frag loads conflict-free).
// Stage: (128 + 128) rows x 36 words = 9216 words = 36KB; 3 stages = 108KB dynamic.
#define ROWW 36
#define AB_WORDS (128 * ROWW)          // 4608 words per operand
#define STG_WORDS (2 * AB_WORDS)       // 9216 words per stage
#define GEMM_SMEM (3 * STG_WORDS * 4)  // 110592 bytes

__device__ __forceinline__ void gemm_pipe(
    const float* __restrict__ Wtf,
    const float* __restrict__ Btf,
    uint32_t* SM, int tid, float (&acc)[2][8][4])
{
    const int lane = tid & 31, wid = tid >> 5;
    const int wm = wid & 3, wn = wid >> 2;
    const int g = lane >> 2, tig = lane & 3;
    const uint32_t smb = smem_u32(SM);

    int gA[4], gB[4];
    uint32_t dA[4], dB[4];
#pragma unroll
    for (int i = 0; i < 4; ++i) {
        int f = tid + i * 256;
        int row = f >> 3, c4 = f & 7;          // 128 rows x 8 16B-chunks (BK=32)
        gA[i] = row * 1024 + c4 * 4;
        gB[i] = (row >> 6) * CP + (row & 63) * 1024 + c4 * 4;
        dA[i] = (uint32_t)(row * ROWW + c4 * 4) * 4;
        dB[i] = dA[i] + AB_WORDS * 4;
    }
    // prologue: stages 0, 1
#pragma unroll
    for (int st = 0; st < 2; ++st) {
        uint32_t base = smb + (uint32_t)st * (STG_WORDS * 4);
        int kc = st * 32;
#pragma unroll
        for (int i = 0; i < 4; ++i) {
            cpa16(base + dA[i], Wtf + gA[i] + kc);
            cpa16(base + dB[i], Btf + gB[i] + kc);
        }
        CP_COMMIT();
    }

    for (int c = 0; c < 32; ++c) {
        if (c + 2 < 32) {
            uint32_t base = smb + (uint32_t)(((c + 2) % 3) * (STG_WORDS * 4));
            int kc = (c + 2) * 32;
#pragma unroll
            for (int i = 0; i < 4; ++i) {
                cpa16(base + dA[i], Wtf + gA[i] + kc);
                cpa16(base + dB[i], Btf + gB[i] + kc);
            }
        }
        CP_COMMIT();
        asm volatile("cp.async.wait_group 2;" ::: "memory");
        __syncthreads();
        const uint32_t* As = SM + (c % 3) * STG_WORDS;
        const uint32_t* Bs = As + AB_WORDS;
#pragma unroll
        for (int s = 0; s < 4; ++s) {
            const int k0 = s * 8;
            uint32_t a[2][4], b[8][2];
#pragma unroll
            for (int mt = 0; mt < 2; ++mt) {
                int r0 = wm * 32 + mt * 16 + g;
                a[mt][0] = As[r0 * ROWW + k0 + tig];
                a[mt][1] = As[(r0 + 8) * ROWW + k0 + tig];
                a[mt][2] = As[r0 * ROWW + k0 + tig + 4];
                a[mt][3] = As[(r0 + 8) * ROWW + k0 + tig + 4];
            }
#pragma unroll
            for (int nt = 0; nt < 8; ++nt) {
                int cc = wn * 64 + nt * 8 + g;
                b[nt][0] = Bs[cc * ROWW + k0 + tig];
                b[nt][1] = Bs[cc * ROWW + k0 + tig + 4];
            }
#pragma unroll
            for (int mt = 0; mt < 2; ++mt)
#pragma unroll
                for (int nt = 0; nt < 8; ++nt)
                    mma8(acc[mt][nt], a[mt], b[nt]);
        }
        __syncthreads();
    }
}

// ---------------- K-1: convert weights to tf32 -------------------------------------
__global__ __launch_bounds__(256) void k_wcvt(
    const float* __restrict__ Wq, const float* __restrict__ Wk,
    const float* __restrict__ Wv, const float* __restrict__ Wp)
{
    const float* src = (blockIdx.y == 0) ? Wq : (blockIdx.y == 1) ? Wk
                     : (blockIdx.y == 2) ? Wv : Wp;
    size_t i4 = (size_t)blockIdx.x * 256 + threadIdx.x;
    float4 v = reinterpret_cast<const float4*>(src)[i4];
    uint4 o = make_uint4(f2tf(v.x), f2tf(v.y), f2tf(v.z), f2tf(v.w));
    reinterpret_cast<uint4*>(g_wtf + (size_t)blockIdx.y * 1048576)[i4] = o;
}

// ---------------- K0: transpose x -> xt [b][p][c] (tf32-rounded) -------------------
__global__ __launch_bounds__(256) void k_xt(const float* __restrict__ x)
{
    __shared__ __align__(16) float S[4096];
    const int tid = threadIdx.x;
    const size_t b = blockIdx.y;
    const int c0 = blockIdx.x * 64;
    const float* xb = x + b * CP + (size_t)c0 * 64;
#pragma unroll
    for (int i = 0; i < 4; ++i) {
        int f = tid + i * 256;
        int c = f >> 4, p0 = (f & 15) * 4;
        float4 v = *reinterpret_cast<const float4*>(xb + (size_t)c * 64 + p0);
        S[(p0 + 0) * 64 + (c ^ (((p0 + 0) & 7) * 4))] = v.x;
        S[(p0 + 1) * 64 + (c ^ (((p0 + 1) & 7) * 4))] = v.y;
        S[(p0 + 2) * 64 + (c ^ (((p0 + 2) & 7) * 4))] = v.z;
        S[(p0 + 3) * 64 + (c ^ (((p0 + 3) & 7) * 4))] = v.w;
    }
    __syncthreads();
    float* ot = g_xt + b * CP;
#pragma unroll
    for (int i = 0; i < 4; ++i) {
        int f = tid + i * 256;
        int p = f >> 4, c4 = (f & 15) * 4;
        float4 v = *reinterpret_cast<const float4*>(S + p * 64 + (c4 ^ ((p & 7) * 4)));
        float4 o = make_float4(f2tff(v.x), f2tff(v.y), f2tff(v.z), f2tff(v.w));
        *reinterpret_cast<float4*>(ot + (size_t)p * 1024 + c0 + c4) = o;
    }
}

// ---------------- K1: fused QKV projection (tf32 tensor cores, pipelined) ----------
__global__ __launch_bounds__(256, 2) void k_qkv_mma(
    const float* __restrict__ bq, const float* __restrict__ bk,
    const float* __restrict__ bv)
{
    extern __shared__ __align__(16) uint32_t SMD[];
    const int tid = threadIdx.x;
    const int bx = blockIdx.x;                 // 0..23
    const int wmat = bx >> 3, tile = bx & 7;
    const int row0 = tile * 128;
    const size_t b0 = (size_t)blockIdx.y * 2;
    const float* bias = (wmat == 0) ? bq : (wmat == 1) ? bk : bv;

    float acc[2][8][4] = {};
    gemm_pipe(g_wtf + (size_t)wmat * 1048576 + (size_t)row0 * 1024,
              g_xt + b0 * CP, SMD, tid, acc);

    const int lane = tid & 31, wid = tid >> 5;
    const int wm = wid & 3, wn = wid >> 2;
    const int g = lane >> 2, tig = lane & 3;
#pragma unroll
    for (int mt = 0; mt < 2; ++mt) {
        int r = row0 + wm * 32 + mt * 16 + g;
        float bv0 = bias[r], bv1 = bias[r + 8];
        float* o0 = g_qkv + ((b0 + wn) * 3 + wmat) * CP + (size_t)r * 64;
        float* o1 = o0 + 8 * 64;
#pragma unroll
        for (int nt = 0; nt < 8; ++nt) {
            int p = nt * 8 + 2 * tig;
            *reinterpret_cast<float2*>(o0 + p) =
                make_float2(acc[mt][nt][0] + bv0, acc[mt][nt][1] + bv0);
            *reinterpret_cast<float2*>(o1 + p) =
                make_float2(acc[mt][nt][2] + bv1, acc[mt][nt][3] + bv1);
        }
    }
}

// ---------------- K2: per-(batch, head) attention (tf32 tensor cores) --------------
// Smem arrays padded to 68-word rows (68 = 4 mod 32 -> frag loads <=2-way).
#define AT_ROW 68
#define AT_MAT (64 * AT_ROW)           // 4352 words
#define ATTN_SMEM (3 * AT_MAT * 4)     // 52224 bytes

__global__ __launch_bounds__(256) void k_attn(const float* __restrict__ temperature)
{
    extern __shared__ __align__(16) float AS[];
    float* Sq = AS;                 // q (normalized, tf32) -> later v (tf32)
    float* Sk = AS + AT_MAT;        // k (normalized, tf32) -> later softmax scratch
    float* Sc = AS + 2 * AT_MAT;    // scores [m][n] fp32 -> P (tf32)
    const int tid = threadIdx.x;
    const int bh = blockIdx.x;
    const int b = bh >> 4, h = bh & 15;
    const float* qg = g_qkv + ((size_t)b * 3 + 0) * CP + h * 4096;
    const float* kg = g_qkv + ((size_t)b * 3 + 1) * CP + h * 4096;
    const float* vg = g_qkv + ((size_t)b * 3 + 2) * CP + h * 4096;

    // load q, k (padded rows)
#pragma unroll
    for (int i = 0; i < 4; ++i) {
        int f = tid + i * 256;
        int d = f >> 4, p0 = (f & 15) * 4;
        *reinterpret_cast<float4*>(Sq + d * AT_ROW + p0) =
            *reinterpret_cast<const float4*>(qg + d * 64 + p0);
        *reinterpret_cast<float4*>(Sk + d * AT_ROW + p0) =
            *reinterpret_cast<const float4*>(kg + d * 64 + p0);
    }
    __syncthreads();

    // L2-normalize each row over 64 spatial positions; store tf32-rounded
    if (tid < 128) {
        float* mat = (tid < 64) ? Sq : Sk;
        int r = tid & 63;
        float s = 0.f;
        for (int i = 0; i < 64; ++i) { int p = (i + r) & 63; float v = mat[r * AT_ROW + p]; s = fmaf(v, v, s); }
        float inv = 1.0f / fmaxf(sqrtf(s), 1e-12f);
        for (int i = 0; i < 64; ++i) { int p = (i + r) & 63; mat[r * AT_ROW + p] = f2tff(mat[r * AT_ROW + p] * inv); }
    }
    __syncthreads();

    const float invT = 1.0f / (temperature[0] + 1e-6f);
    const int lane = tid & 31, wid = tid >> 5;
    const int wm = wid & 3, wn = wid >> 2;
    const int g = lane >> 2, tig = lane & 3;
    const int m0 = wm * 16, n0 = wn * 32;

    // GEMM1: scores[m][n] = sum_d k[d][m] q[d][n]  (A = K^T, B = Q)
    {
        float acc[4][4] = {};
#pragma unroll
        for (int s = 0; s < 8; ++s) {
            int k0 = s * 8;
            uint32_t a[4];
            a[0] = __float_as_uint(Sk[(k0 + tig) * AT_ROW + m0 + g]);
            a[1] = __float_as_uint(Sk[(k0 + tig) * AT_ROW + m0 + 8 + g]);
            a[2] = __float_as_uint(Sk[(k0 + tig + 4) * AT_ROW + m0 + g]);
            a[3] = __float_as_uint(Sk[(k0 + tig + 4) * AT_ROW + m0 + 8 + g]);
#pragma unroll
            for (int nt = 0; nt < 4; ++nt) {
                uint32_t bb[2];
                bb[0] = __float_as_uint(Sq[(k0 + tig) * AT_ROW + n0 + nt * 8 + g]);
                bb[1] = __float_as_uint(Sq[(k0 + tig + 4) * AT_ROW + n0 + nt * 8 + g]);
                mma8(acc[nt], a, bb);
            }
        }
#pragma unroll
        for (int nt = 0; nt < 4; ++nt) {
            int col = n0 + nt * 8 + 2 * tig;
            Sc[(m0 + g) * AT_ROW + col]     = acc[nt][0] * invT;
            Sc[(m0 + g) * AT_ROW + col + 1] = acc[nt][1] * invT;
            Sc[(m0 + 8 + g) * AT_ROW + col]     = acc[nt][2] * invT;
            Sc[(m0 + 8 + g) * AT_ROW + col + 1] = acc[nt][3] * invT;
        }
    }
    __syncthreads();

    // load v into Sq (tf32-rounded); independent of softmax below
#pragma unroll
    for (int i = 0; i < 4; ++i) {
        int f = tid + i * 256;
        int d = f >> 4, p0 = (f & 15) * 4;
        float4 v = *reinterpret_cast<const float4*>(vg + d * 64 + p0);
        float4 o = make_float4(f2tff(v.x), f2tff(v.y), f2tff(v.z), f2tff(v.w));
        *reinterpret_cast<float4*>(Sq + d * AT_ROW + p0) = o;
    }

    // softmax over m (rows of Sc) per column n; scratch in Sk; P stored tf32-rounded
    {
        const int n = tid & 63, sub = tid >> 6;
        float mx = -1e30f;
#pragma unroll
        for (int i = 0; i < 16; ++i) mx = fmaxf(mx, Sc[(sub * 16 + i) * AT_ROW + n]);
        Sk[sub * 64 + n] = mx;
        __syncthreads();
        float gmx = fmaxf(fmaxf(Sk[n], Sk[64 + n]), fmaxf(Sk[128 + n], Sk[192 + n]));
        __syncthreads();
        float ssum = 0.f;
#pragma unroll
        for (int i = 0; i < 16; ++i) {
            float e = __expf(Sc[(sub * 16 + i) * AT_ROW + n] - gmx);
            Sc[(sub * 16 + i) * AT_ROW + n] = e;
            ssum += e;
        }
        Sk[sub * 64 + n] = ssum;
        __syncthreads();
        float inv = 1.0f / (Sk[n] + Sk[64 + n] + Sk[128 + n] + Sk[192 + n]);
#pragma unroll
        for (int i = 0; i < 16; ++i) {
            int idx = (sub * 16 + i) * AT_ROW + n;
            Sc[idx] = f2tff(Sc[idx] * inv);
        }
    }
    __syncthreads();

    // GEMM2: D[n][dd] = sum_m P[m][n] * V[dd][m]   (A = P^T, B = V^T; both native layouts)
    {
        float oc[4][4] = {};
#pragma unroll
        for (int s = 0; s < 8; ++s) {
            int k0 = s * 8;
            uint32_t a[4];
            a[0] = __float_as_uint(Sc[(k0 + tig) * AT_ROW + m0 + g]);
            a[1] = __float_as_uint(Sc[(k0 + tig) * AT_ROW + m0 + 8 + g]);
            a[2] = __float_as_uint(Sc[(k0 + tig + 4) * AT_ROW + m0 + g]);
            a[3] = __float_as_uint(Sc[(k0 + tig + 4) * AT_ROW + m0 + 8 + g]);
#pragma unroll
            for (int nt = 0; nt < 4; ++nt) {
                uint32_t bb[2];
                bb[0] = __float_as_uint(Sq[(n0 + nt * 8 + g) * AT_ROW + k0 + tig]);
                bb[1] = __float_as_uint(Sq[(n0 + nt * 8 + g) * AT_ROW + k0 + tig + 4]);
                mma8(oc[nt], a, bb);
            }
        }
        // D rows = spatial n, cols = head dim dd; write straight to g_aT[b][p][h*64+dd]
        float* og = g_aT + (size_t)b * CP + h * 64;
        const int n1 = m0 + g, n2 = m0 + 8 + g;
#pragma unroll
        for (int nt = 0; nt < 4; ++nt) {
            int dd = n0 + nt * 8 + 2 * tig;
            *reinterpret_cast<float2*>(og + (size_t)n1 * 1024 + dd) =
                make_float2(f2tff(oc[nt][0]), f2tff(oc[nt][1]));
            *reinterpret_cast<float2*>(og + (size_t)n2 * 1024 + dd) =
                make_float2(f2tff(oc[nt][2]), f2tff(oc[nt][3]));
        }
    }
}

// ---------------- K3: output projection + residual + LN partials -------------------
__global__ __launch_bounds__(256, 2) void k_proj_mma(
    const float* __restrict__ x,
    const float* __restrict__ bp, const float* __restrict__ gamma)
{
    extern __shared__ __align__(16) uint32_t SMD[];
    __shared__ float red[16];
    const int tid = threadIdx.x;
    const int tile = blockIdx.x;               // 0..7
    const int row0 = tile * 128;
    const size_t b0 = (size_t)blockIdx.y * 2;

    float acc[2][8][4] = {};
    gemm_pipe(g_wtf + (size_t)3 * 1048576 + (size_t)row0 * 1024,
              g_aT + b0 * CP, SMD, tid, acc);

    const int lane = tid & 31, wid = tid >> 5;
    const int wm = wid & 3, wn = wid >> 2;
    const int g = lane >> 2, tig = lane & 3;
    const float gam = gamma[0];
    const float g1 = 1.0f - gam;
    float ls = 0.f, lq = 0.f;
#pragma unroll
    for (int mt = 0; mt < 2; ++mt) {
        int r = row0 + wm * 32 + mt * 16 + g;
        float bb0 = bp[r], bb1 = bp[r + 8];
        size_t base = (b0 + wn) * CP + (size_t)r * 64;
#pragma unroll
        for (int nt = 0; nt < 8; ++nt) {
            int p = nt * 8 + 2 * tig;
            float2 x0 = *reinterpret_cast<const float2*>(x + base + p);
            float2 x1 = *reinterpret_cast<const float2*>(x + base + 8 * 64 + p);
            float2 v0, v1;
            v0.x = gam * (acc[mt][nt][0] + bb0) + g1 * x0.x;
            v0.y = gam * (acc[mt][nt][1] + bb0) + g1 * x0.y;
            v1.x = gam * (acc[mt][nt][2] + bb1) + g1 * x1.x;
            v1.y = gam * (acc[mt][nt][3] + bb1) + g1 * x1.y;
            *reinterpret_cast<float2*>(g_res + base + p) = v0;
            *reinterpret_cast<float2*>(g_res + base + 8 * 64 + p) = v1;
            ls += v0.x + v0.y + v1.x + v1.y;
            lq += v0.x * v0.x + v0.y * v0.y + v1.x * v1.x + v1.y * v1.y;
        }
    }
#pragma unroll
    for (int off = 16; off; off >>= 1) {
        ls += __shfl_xor_sync(0xFFFFFFFFu, ls, off);
        lq += __shfl_xor_sync(0xFFFFFFFFu, lq, off);
    }
    if (lane == 0) { red[wid * 2] = ls; red[wid * 2 + 1] = lq; }
    __syncthreads();
    if (tid == 0) {
        float s0 = 0.f, q0 = 0.f, s1 = 0.f, q1 = 0.f;
#pragma unroll
        for (int w = 0; w < 4; ++w) {
            s0 += red[w * 2];     q0 += red[w * 2 + 1];
            s1 += red[8 + w * 2]; q1 += red[8 + w * 2 + 1];
        }
        g_psum[(b0 + 0) * 8 + tile] = s0; g_psumsq[(b0 + 0) * 8 + tile] = q0;
        g_psum[(b0 + 1) * 8 + tile] = s1; g_psumsq[(b0 + 1) * 8 + tile] = q1;
    }
}

// ---------------- K4: per-batch LN stats ------------------------------------------
__global__ void k_stats()
{
    int b = blockIdx.x * blockDim.x + threadIdx.x;
    if (b < Bn) {
        float s = 0.f, q = 0.f;
#pragma unroll
        for (int t = 0; t < 8; ++t) { s += g_psum[b * 8 + t]; q += g_psumsq[b * 8 + t]; }
        float mean = s * (1.0f / 65536.0f);
        float var = q * (1.0f / 65536.0f) - mean * mean;
        g_mean[b] = mean;
        g_rinv[b] = rsqrtf(var + 1e-5f);
    }
}

// ---------------- K5: LayerNorm apply ---------------------------------------------
__global__ __launch_bounds__(256) void k_ln(
    const float* __restrict__ ln_w, const float* __restrict__ ln_b,
    float* __restrict__ out)
{
    size_t i4 = (size_t)blockIdx.x * 256 + threadIdx.x;
    int b = (int)(i4 >> 14);
    int cp = (int)(i4 & 16383);
    float mean = g_mean[b], inv = g_rinv[b];
    float4 r  = reinterpret_cast<const float4*>(g_res)[i4];
    float4 w  = reinterpret_cast<const float4*>(ln_w)[cp];
    float4 lb = reinterpret_cast<const float4*>(ln_b)[cp];
    float4 o;
    o.x = (r.x - mean) * inv * w.x + lb.x;
    o.y = (r.y - mean) * inv * w.y + lb.y;
    o.z = (r.z - mean) * inv * w.z + lb.z;
    o.w = (r.w - mean) * inv * w.w + lb.w;
    reinterpret_cast<float4*>(out)[i4] = o;
}

// ---------------- launch -----------------------------------------------------------
extern "C" void kernel_launch(void* const* d_in, const int* in_sizes, int n_in,
                              void* d_out, int out_size)
{
    (void)in_sizes; (void)n_in; (void)out_size;
    const float* x     = (const float*)d_in[0];
    const float* Wq    = (const float*)d_in[1];
    const float* bq    = (const float*)d_in[2];
    const float* Wk    = (const float*)d_in[3];
    const float* bk    = (const float*)d_in[4];
    const float* Wv    = (const float*)d_in[5];
    const float* bv    = (const float*)d_in[6];
    const float* Wp    = (const float*)d_in[7];
    const float* bp    = (const float*)d_in[8];
    const float* gamma = (const float*)d_in[9];
    const float* temp  = (const float*)d_in[10];
    const float* lnw   = (const float*)d_in[11];
    const float* lnb   = (const float*)d_in[12];
    float* out = (float*)d_out;

    cudaFuncSetAttribute(k_qkv_mma,  cudaFuncAttributeMaxDynamicSharedMemorySize, GEMM_SMEM);
    cudaFuncSetAttribute(k_proj_mma, cudaFuncAttributeMaxDynamicSharedMemorySize, GEMM_SMEM);
    cudaFuncSetAttribute(k_attn,     cudaFuncAttributeMaxDynamicSharedMemorySize, ATTN_SMEM);

    dim3 gw(1024, 4);
    k_wcvt<<<gw, 256>>>(Wq, Wk, Wv, Wp);
    dim3 gx(16, Bn);
    k_xt<<<gx, 256>>>(x);
    dim3 g1(24, Bn / 2);
    k_qkv_mma<<<g1, 256, GEMM_SMEM>>>(bq, bk, bv);
    k_attn<<<Bn * 16, 256, ATTN_SMEM>>>(temp);
    dim3 g3(8, Bn / 2);
    k_proj_mma<<<g3, 256, GEMM_SMEM>>>(x, bp, gamma);
    k_stats<<<1, 1024>>>();
    k_ln<<<65536, 256>>>(lnw, lnb, out);
}